// round 1
// baseline (speedup 1.0000x reference)
#include <cuda_runtime.h>
#include <cuda_bf16.h>
#include <cstdint>
#include <math.h>

#define N_ROWS 8192
#define M_COLS 8192
#define D_K    256

#define BM 128
#define BN 128
#define BK 32
#define PITCH 40   // bf16 elems per smem row (32 data + 8 pad)

// Scratch + accumulators (no cudaMalloc allowed)
__device__ __nv_bfloat16 g_A[N_ROWS * D_K];
__device__ __nv_bfloat16 g_B[M_COLS * D_K];
__device__ double g_pos_sum;
__device__ double g_neg_sum;
__device__ unsigned long long g_pos_cnt;
__device__ unsigned long long g_neg_cnt;

// ---------------------------------------------------------------------------
// Kernel 1: zero accumulators + convert fp32 -> bf16
// ---------------------------------------------------------------------------
__global__ void convert_zero_kernel(const float* __restrict__ img,
                                    const float* __restrict__ txt) {
    int i = blockIdx.x * blockDim.x + threadIdx.x;
    if (i == 0) {
        g_pos_sum = 0.0;
        g_neg_sum = 0.0;
        g_pos_cnt = 0ull;
        g_neg_cnt = 0ull;
    }
    const int n = N_ROWS * D_K;
    // 4 elements per thread, vectorized
    int base = i * 4;
    if (base < n) {
        float4 a = *reinterpret_cast<const float4*>(img + base);
        float4 b = *reinterpret_cast<const float4*>(txt + base);
        __nv_bfloat162* pa = reinterpret_cast<__nv_bfloat162*>(&g_A[base]);
        __nv_bfloat162* pb = reinterpret_cast<__nv_bfloat162*>(&g_B[base]);
        pa[0] = __floats2bfloat162_rn(a.x, a.y);
        pa[1] = __floats2bfloat162_rn(a.z, a.w);
        pb[0] = __floats2bfloat162_rn(b.x, b.y);
        pb[1] = __floats2bfloat162_rn(b.z, b.w);
    }
}

// ---------------------------------------------------------------------------
// Kernel 2: fused GEMM (bf16 mma.sync) + masked-exp reduction epilogue
// 256 threads = 8 warps arranged 4 (m) x 2 (n); warp tile = 32x64
// ---------------------------------------------------------------------------
__global__ __launch_bounds__(256) void fused_msloss_kernel(
    const int* __restrict__ gt_pre, const int* __restrict__ gt_map) {

    __shared__ __align__(16) __nv_bfloat16 sA[BM * PITCH];
    __shared__ __align__(16) __nv_bfloat16 sB[BN * PITCH];
    __shared__ int rl[BM];
    __shared__ int cl[BN];

    const int tid  = threadIdx.x;
    const int wid  = tid >> 5;
    const int lane = tid & 31;
    const int warp_m = wid & 3;   // 0..3 -> rows
    const int warp_n = wid >> 2;  // 0..1 -> cols
    const int row0 = blockIdx.x * BM;
    const int col0 = blockIdx.y * BN;

    // label tiles
    if (tid < BM) rl[tid] = gt_pre[row0 + tid];
    else          cl[tid - BM] = gt_map[col0 + (tid - BM)];

    float acc[2][8][4];
    #pragma unroll
    for (int i = 0; i < 2; i++)
        #pragma unroll
        for (int j = 0; j < 8; j++)
            #pragma unroll
            for (int r = 0; r < 4; r++) acc[i][j][r] = 0.f;

    const uint32_t sA_u = (uint32_t)__cvta_generic_to_shared(sA);
    const uint32_t sB_u = (uint32_t)__cvta_generic_to_shared(sB);

    for (int k0 = 0; k0 < D_K; k0 += BK) {
        __syncthreads();   // protect smem from previous iteration's reads (and label stores, iter 0)
        // Load A,B tiles: 128 rows x 32 bf16 each == 512 16B segments per matrix
        #pragma unroll
        for (int i = 0; i < 2; i++) {
            int id  = tid + i * 256;
            int r   = id >> 2;
            int seg = id & 3;
            *reinterpret_cast<uint4*>(&sA[r * PITCH + seg * 8]) =
                *reinterpret_cast<const uint4*>(&g_A[(size_t)(row0 + r) * D_K + k0 + seg * 8]);
            *reinterpret_cast<uint4*>(&sB[r * PITCH + seg * 8]) =
                *reinterpret_cast<const uint4*>(&g_B[(size_t)(col0 + r) * D_K + k0 + seg * 8]);
        }
        __syncthreads();

        #pragma unroll
        for (int ks = 0; ks < 2; ks++) {
            // A fragments: 2 m16 tiles
            uint32_t a[2][4];
            #pragma unroll
            for (int mt = 0; mt < 2; mt++) {
                int rrow = warp_m * 32 + mt * 16 + (lane & 15);
                int kcol = ks * 16 + (lane >> 4) * 8;
                uint32_t addr = sA_u + (uint32_t)(rrow * PITCH + kcol) * 2u;
                asm volatile(
                    "ldmatrix.sync.aligned.m8n8.x4.shared.b16 {%0,%1,%2,%3}, [%4];"
                    : "=r"(a[mt][0]), "=r"(a[mt][1]), "=r"(a[mt][2]), "=r"(a[mt][3])
                    : "r"(addr));
            }
            // B fragments: 8 n8 tiles, loaded as 4 x (x4) covering 2 tiles each.
            // B stored [n][k] (k-contiguous) == col-major B for mma "row.col" -> NO .trans
            uint32_t b[4][4];
            #pragma unroll
            for (int np = 0; np < 4; np++) {
                int nrow = warp_n * 64 + np * 16 + ((lane >> 4) * 8) + (lane & 7);
                int kcol = ks * 16 + (((lane >> 3) & 1) * 8);
                uint32_t addr = sB_u + (uint32_t)(nrow * PITCH + kcol) * 2u;
                asm volatile(
                    "ldmatrix.sync.aligned.m8n8.x4.shared.b16 {%0,%1,%2,%3}, [%4];"
                    : "=r"(b[np][0]), "=r"(b[np][1]), "=r"(b[np][2]), "=r"(b[np][3])
                    : "r"(addr));
            }
            #pragma unroll
            for (int mt = 0; mt < 2; mt++) {
                #pragma unroll
                for (int nt = 0; nt < 8; nt++) {
                    const uint32_t* bb = &b[nt >> 1][(nt & 1) * 2];
                    float* c = acc[mt][nt];
                    asm volatile(
                        "mma.sync.aligned.m16n8k16.row.col.f32.bf16.bf16.f32 "
                        "{%0,%1,%2,%3}, {%4,%5,%6,%7}, {%8,%9}, {%0,%1,%2,%3};"
                        : "+f"(c[0]), "+f"(c[1]), "+f"(c[2]), "+f"(c[3])
                        : "r"(a[mt][0]), "r"(a[mt][1]), "r"(a[mt][2]), "r"(a[mt][3]),
                          "r"(bb[0]), "r"(bb[1]));
                }
            }
        }
    }

    // ---------------- Epilogue: masked exp + per-thread accumulate -------------
    float pos_s = 0.f, neg_s = 0.f;
    int   pos_c = 0,   neg_c = 0;

    const int rbase = warp_m * 32 + (lane >> 2);
    const int cbase = warp_n * 64 + ((lane & 3) << 1);

    #pragma unroll
    for (int mt = 0; mt < 2; mt++) {
        #pragma unroll
        for (int nt = 0; nt < 8; nt++) {
            #pragma unroll
            for (int r = 0; r < 4; r++) {
                float s = acc[mt][nt][r];
                if (s > 0.f) {
                    int rrow = rbase + mt * 16 + ((r >> 1) << 3);
                    int ccol = cbase + nt * 8 + (r & 1);
                    bool z = (rl[rrow] == cl[ccol]);
                    float t = s - 0.5f;
                    if (z) { pos_s += __expf(-2.0f * t); pos_c++; }
                    else   { neg_s += __expf(40.0f * t); neg_c++; }
                }
            }
        }
    }

    // warp reduction
    #pragma unroll
    for (int o = 16; o > 0; o >>= 1) {
        pos_s += __shfl_xor_sync(0xffffffffu, pos_s, o);
        neg_s += __shfl_xor_sync(0xffffffffu, neg_s, o);
        pos_c += __shfl_xor_sync(0xffffffffu, pos_c, o);
        neg_c += __shfl_xor_sync(0xffffffffu, neg_c, o);
    }
    if (lane == 0) {
        atomicAdd(&g_pos_sum, (double)pos_s);
        atomicAdd(&g_neg_sum, (double)neg_s);
        atomicAdd(&g_pos_cnt, (unsigned long long)pos_c);
        atomicAdd(&g_neg_cnt, (unsigned long long)neg_c);
    }
}

// ---------------------------------------------------------------------------
// Kernel 3: finalize scalar
// ---------------------------------------------------------------------------
__global__ void finalize_kernel(float* __restrict__ out) {
    double pl = 0.0, nl = 0.0;
    if (g_pos_cnt > 0ull) pl = log1p(g_pos_sum) / (2.0  * (double)g_pos_cnt);
    if (g_neg_cnt > 0ull) nl = log1p(g_neg_sum) / (40.0 * (double)g_neg_cnt);
    out[0] = (float)(pl + nl);
}

// ---------------------------------------------------------------------------
extern "C" void kernel_launch(void* const* d_in, const int* in_sizes, int n_in,
                              void* d_out, int out_size) {
    const float* img    = (const float*)d_in[0];
    const float* txt    = (const float*)d_in[1];
    const int*   gt_pre = (const int*)d_in[2];
    const int*   gt_map = (const int*)d_in[3];

    const int n_elems = N_ROWS * D_K;            // per matrix
    int threads = 256;
    int blocks = (n_elems / 4 + threads - 1) / threads;
    convert_zero_kernel<<<blocks, threads>>>(img, txt);

    dim3 grid(N_ROWS / BM, M_COLS / BN);         // 64 x 64
    fused_msloss_kernel<<<grid, 256>>>(gt_pre, gt_map);

    finalize_kernel<<<1, 1>>>((float*)d_out);
}

// round 3
// speedup vs baseline: 1.2942x; 1.2942x over previous
#include <cuda_runtime.h>
#include <cuda_bf16.h>
#include <cstdint>
#include <math.h>

#define N_ROWS 8192
#define M_COLS 8192
#define D_K    256

#define BM 128
#define BN 128
#define BK 32
#define PITCH 40            // bf16 elems per smem row (32 data + 8 pad) -> 80 B
#define STAGES 4
#define K_ITERS (D_K / BK)  // 8

#define STAGE_ELEMS (BM * PITCH)          // per matrix: 5120 elems = 10240 B
#define STAGE_BYTES (2 * STAGE_ELEMS * 2) // A + B = 20480 B
#define SMEM_TOTAL  (STAGES * STAGE_BYTES) // 81920 B dynamic

// Scratch + accumulators (no cudaMalloc allowed)
__device__ __nv_bfloat16 g_A[N_ROWS * D_K];
__device__ __nv_bfloat16 g_B[M_COLS * D_K];
__device__ double g_pos_sum;
__device__ double g_neg_sum;
__device__ unsigned long long g_pos_cnt;
__device__ unsigned long long g_neg_cnt;

__device__ __forceinline__ uint32_t smem_u32(const void* p) {
    uint32_t a;
    asm("{ .reg .u64 t; cvta.to.shared.u64 t, %1; cvt.u32.u64 %0, t; }" : "=r"(a) : "l"(p));
    return a;
}
__device__ __forceinline__ void cp_async16(uint32_t dst, const void* src) {
    asm volatile("cp.async.cg.shared.global [%0], [%1], 16;" :: "r"(dst), "l"(src) : "memory");
}
__device__ __forceinline__ void cp_commit() {
    asm volatile("cp.async.commit_group;" ::: "memory");
}
template <int N>
__device__ __forceinline__ void cp_wait() {
    asm volatile("cp.async.wait_group %0;" :: "n"(N) : "memory");
}

// ---------------------------------------------------------------------------
// Kernel 1: zero accumulators + convert fp32 -> bf16
// ---------------------------------------------------------------------------
__global__ void convert_zero_kernel(const float* __restrict__ img,
                                    const float* __restrict__ txt) {
    int i = blockIdx.x * blockDim.x + threadIdx.x;
    if (i == 0) {
        g_pos_sum = 0.0; g_neg_sum = 0.0;
        g_pos_cnt = 0ull; g_neg_cnt = 0ull;
    }
    const int n = N_ROWS * D_K;
    int base = i * 4;
    if (base < n) {
        float4 a = *reinterpret_cast<const float4*>(img + base);
        float4 b = *reinterpret_cast<const float4*>(txt + base);
        __nv_bfloat162* pa = reinterpret_cast<__nv_bfloat162*>(&g_A[base]);
        __nv_bfloat162* pb = reinterpret_cast<__nv_bfloat162*>(&g_B[base]);
        pa[0] = __floats2bfloat162_rn(a.x, a.y);
        pa[1] = __floats2bfloat162_rn(a.z, a.w);
        pb[0] = __floats2bfloat162_rn(b.x, b.y);
        pb[1] = __floats2bfloat162_rn(b.z, b.w);
    }
}

// ---------------------------------------------------------------------------
// Kernel 2: pipelined bf16 mma.sync GEMM + fused masked-exp reduction
// 256 threads = 8 warps (4m x 2n); warp tile 32x64; 4-stage cp.async pipeline
// ---------------------------------------------------------------------------
__global__ void __launch_bounds__(256, 2) fused_msloss_kernel(
    const int* __restrict__ gt_pre, const int* __restrict__ gt_map) {

    extern __shared__ __align__(128) char smem[];
    __shared__ int rl[BM];
    __shared__ int cl[BN];

    const int tid  = threadIdx.x;
    const int wid  = tid >> 5;
    const int lane = tid & 31;
    const int warp_m = wid & 3;
    const int warp_n = wid >> 2;
    const int row0 = blockIdx.x * BM;
    const int col0 = blockIdx.y * BN;

    if (tid < BM) rl[tid] = gt_pre[row0 + tid];
    else          cl[tid - BM] = gt_map[col0 + (tid - BM)];

    float acc[2][8][4];
    #pragma unroll
    for (int i = 0; i < 2; i++)
        #pragma unroll
        for (int j = 0; j < 8; j++)
            #pragma unroll
            for (int r = 0; r < 4; r++) acc[i][j][r] = 0.f;

    const uint32_t sm_u = smem_u32(smem);

    // per-thread load geometry: 2 segments per matrix per stage
    // seg_id = tid + i*256 ; row = seg_id>>2 ; seg = seg_id&3
    const int lrow0 = tid >> 2;
    const int lseg  = tid & 3;

    const __nv_bfloat16* gA = g_A + (size_t)row0 * D_K;
    const __nv_bfloat16* gB = g_B + (size_t)col0 * D_K;

    auto load_stage = [&](int kiter) {
        if (kiter < K_ITERS) {
            const int st = kiter & (STAGES - 1);
            const uint32_t sa = sm_u + st * STAGE_BYTES;
            const uint32_t sb = sa + STAGE_ELEMS * 2;
            const int k0 = kiter * BK;
            #pragma unroll
            for (int i = 0; i < 2; i++) {
                const int row = lrow0 + i * 64;
                const uint32_t doff = (uint32_t)(row * PITCH + lseg * 8) * 2u;
                cp_async16(sa + doff, gA + (size_t)row * D_K + k0 + lseg * 8);
                cp_async16(sb + doff, gB + (size_t)row * D_K + k0 + lseg * 8);
            }
        }
        cp_commit();
    };

    // preload stages 0..2
    load_stage(0);
    load_stage(1);
    load_stage(2);

    #pragma unroll
    for (int kk = 0; kk < K_ITERS; kk++) {
        cp_wait<STAGES - 2>();
        __syncthreads();
        load_stage(kk + STAGES - 1);

        const int st = kk & (STAGES - 1);
        const uint32_t sA_u = sm_u + st * STAGE_BYTES;
        const uint32_t sB_u = sA_u + STAGE_ELEMS * 2;

        #pragma unroll
        for (int ks = 0; ks < 2; ks++) {
            uint32_t a[2][4];
            #pragma unroll
            for (int mt = 0; mt < 2; mt++) {
                int rrow = warp_m * 32 + mt * 16 + (lane & 15);
                int kcol = ks * 16 + (lane >> 4) * 8;
                uint32_t addr = sA_u + (uint32_t)(rrow * PITCH + kcol) * 2u;
                asm volatile(
                    "ldmatrix.sync.aligned.m8n8.x4.shared.b16 {%0,%1,%2,%3}, [%4];"
                    : "=r"(a[mt][0]), "=r"(a[mt][1]), "=r"(a[mt][2]), "=r"(a[mt][3])
                    : "r"(addr));
            }
            uint32_t b[4][4];
            #pragma unroll
            for (int np = 0; np < 4; np++) {
                int nrow = warp_n * 64 + np * 16 + ((lane >> 4) * 8) + (lane & 7);
                int kcol = ks * 16 + (((lane >> 3) & 1) * 8);
                uint32_t addr = sB_u + (uint32_t)(nrow * PITCH + kcol) * 2u;
                asm volatile(
                    "ldmatrix.sync.aligned.m8n8.x4.shared.b16 {%0,%1,%2,%3}, [%4];"
                    : "=r"(b[np][0]), "=r"(b[np][1]), "=r"(b[np][2]), "=r"(b[np][3])
                    : "r"(addr));
            }
            #pragma unroll
            for (int mt = 0; mt < 2; mt++) {
                #pragma unroll
                for (int nt = 0; nt < 8; nt++) {
                    const uint32_t* bb = &b[nt >> 1][(nt & 1) * 2];
                    float* c = acc[mt][nt];
                    asm volatile(
                        "mma.sync.aligned.m16n8k16.row.col.f32.bf16.bf16.f32 "
                        "{%0,%1,%2,%3}, {%4,%5,%6,%7}, {%8,%9}, {%0,%1,%2,%3};"
                        : "+f"(c[0]), "+f"(c[1]), "+f"(c[2]), "+f"(c[3])
                        : "r"(a[mt][0]), "r"(a[mt][1]), "r"(a[mt][2]), "r"(a[mt][3]),
                          "r"(bb[0]), "r"(bb[1]));
                }
            }
        }
    }

    // ---------------- Epilogue: masked exp + per-thread accumulate ------------
    float pos_s = 0.f, neg_s = 0.f;
    int   pos_c = 0,   neg_c = 0;

    const int rbase = warp_m * 32 + (lane >> 2);
    const int cbase = warp_n * 64 + ((lane & 3) << 1);

    #pragma unroll
    for (int mt = 0; mt < 2; mt++) {
        #pragma unroll
        for (int nt = 0; nt < 8; nt++) {
            #pragma unroll
            for (int r = 0; r < 4; r++) {
                float s = acc[mt][nt][r];
                if (s > 0.f) {
                    int rrow = rbase + mt * 16 + ((r >> 1) << 3);
                    int ccol = cbase + nt * 8 + (r & 1);
                    bool z = (rl[rrow] == cl[ccol]);
                    float t = s - 0.5f;
                    if (z) { pos_s += __expf(-2.0f * t); pos_c++; }
                    else   { neg_s += __expf(40.0f * t); neg_c++; }
                }
            }
        }
    }

    #pragma unroll
    for (int o = 16; o > 0; o >>= 1) {
        pos_s += __shfl_xor_sync(0xffffffffu, pos_s, o);
        neg_s += __shfl_xor_sync(0xffffffffu, neg_s, o);
        pos_c += __shfl_xor_sync(0xffffffffu, pos_c, o);
        neg_c += __shfl_xor_sync(0xffffffffu, neg_c, o);
    }
    if (lane == 0) {
        atomicAdd(&g_pos_sum, (double)pos_s);
        atomicAdd(&g_neg_sum, (double)neg_s);
        atomicAdd(&g_pos_cnt, (unsigned long long)pos_c);
        atomicAdd(&g_neg_cnt, (unsigned long long)neg_c);
    }
}

// ---------------------------------------------------------------------------
// Kernel 3: finalize scalar
// ---------------------------------------------------------------------------
__global__ void finalize_kernel(float* __restrict__ out) {
    double pl = 0.0, nl = 0.0;
    if (g_pos_cnt > 0ull) pl = log1p(g_pos_sum) / (2.0  * (double)g_pos_cnt);
    if (g_neg_cnt > 0ull) nl = log1p(g_neg_sum) / (40.0 * (double)g_neg_cnt);
    out[0] = (float)(pl + nl);
}

// ---------------------------------------------------------------------------
extern "C" void kernel_launch(void* const* d_in, const int* in_sizes, int n_in,
                              void* d_out, int out_size) {
    const float* img    = (const float*)d_in[0];
    const float* txt    = (const float*)d_in[1];
    const int*   gt_pre = (const int*)d_in[2];
    const int*   gt_map = (const int*)d_in[3];

    cudaFuncSetAttribute(fused_msloss_kernel,
                         cudaFuncAttributeMaxDynamicSharedMemorySize, SMEM_TOTAL);

    const int n_elems = N_ROWS * D_K;
    int threads = 256;
    int blocks = (n_elems / 4 + threads - 1) / threads;
    convert_zero_kernel<<<blocks, threads>>>(img, txt);

    dim3 grid(N_ROWS / BM, M_COLS / BN);   // 64 x 64
    fused_msloss_kernel<<<grid, 256, SMEM_TOTAL>>>(gt_pre, gt_map);

    finalize_kernel<<<1, 1>>>((float*)d_out);
}